// round 4
// baseline (speedup 1.0000x reference)
#include <cuda_runtime.h>
#include <math.h>

#define BATCH 512
#define NFEAT 128
#define NTRIP 1024
#define KB 8
#define NGRAM 128            // gram blocks (4 antithetic a-values each)
#define NMG 64               // mgram blocks (8 a-values each)
#define NPART (NGRAM + NMG)  // 192 partial slots
#define NTBLK 4
#define NPAIR 8128           // 128*127/2

typedef unsigned long long ull;

// ---------------- device scratch (no allocations allowed) --------------------
__device__ float g_m[BATCH * NFEAT];                // m[a][f] row means of D
__device__ float g_g[NFEAT];                        // g[f] grand mean
__device__ float g_part[NPART * NFEAT * NFEAT];     // split-K partials (S'/2)
__device__ float g_S4[4 * NFEAT * NFEAT];           // 4-way k-split sums
__device__ float g_tpart[NTBLK];                    // triplet partials

// ---- K1: row means, 4 a-values per block (b-row reuse) ----------------------
__global__ void k_means(const float* __restrict__ emb) {
    int blk = blockIdx.x;            // 0..127
    int f = threadIdx.x;             // 0..127
    int a0 = blk * 4;
    float xa0 = emb[(a0 + 0) * NFEAT + f];
    float xa1 = emb[(a0 + 1) * NFEAT + f];
    float xa2 = emb[(a0 + 2) * NFEAT + f];
    float xa3 = emb[(a0 + 3) * NFEAT + f];
    float s0 = 0.f, s1 = 0.f, s2 = 0.f, s3 = 0.f;
#pragma unroll 4
    for (int b = 0; b < BATCH; b++) {
        float v = emb[b * NFEAT + f];
        s0 += fabsf(xa0 - v);
        s1 += fabsf(xa1 - v);
        s2 += fabsf(xa2 - v);
        s3 += fabsf(xa3 - v);
    }
    g_m[(a0 + 0) * NFEAT + f] = s0 * (1.f / BATCH);
    g_m[(a0 + 1) * NFEAT + f] = s1 * (1.f / BATCH);
    g_m[(a0 + 2) * NFEAT + f] = s2 * (1.f / BATCH);
    g_m[(a0 + 3) * NFEAT + f] = s3 * (1.f / BATCH);
}

// ---- K2: g[f] = mean_a m[a][f] ---------------------------------------------
__global__ void k_g(const float* __restrict__ emb) {
    int f = threadIdx.x;
    float s = 0.f;
#pragma unroll 8
    for (int a = 0; a < BATCH; a++) s += g_m[a * NFEAT + f];
    g_g[f] = s * (1.f / BATCH);
    (void)emb;
}

// ---- K3: T/2 partials with packed f32x2 FMAs --------------------------------
__global__ void __launch_bounds__(256) k_gram(const float* __restrict__ emb) {
    const int blk = blockIdx.x;
    int alist[4] = {2 * blk, 2 * blk + 1, 510 - 2 * blk, 511 - 2 * blk};

    __shared__ float s_xa[NFEAT];
    __shared__ float s_v[KB][NFEAT];

    const int tid = threadIdx.x;
    const int ty = tid >> 4, tx = tid & 15;
    const int ib = ty * 8, jb = tx * 8;

    ull acc2[32];                      // 8 rows x 4 f32x2 pairs
#pragma unroll
    for (int c = 0; c < 32; c++) acc2[c] = 0ULL;

#pragma unroll 1
    for (int ai = 0; ai < 4; ai++) {
        const int a = alist[ai];
        if (tid < NFEAT) s_xa[tid] = emb[a * NFEAT + tid];
        __syncthreads();

        const int bstart = (a + 1) & ~(KB - 1);
#pragma unroll 1
        for (int b0 = bstart; b0 < BATCH; b0 += KB) {
#pragma unroll
            for (int t = 0; t < 4; t++) {
                int e = tid + t * 256;
                int kb = e >> 7, f = e & 127;
                int b = b0 + kb;
                float val = 0.f;
                if (b > a) val = fabsf(s_xa[f] - emb[b * NFEAT + f]);
                s_v[kb][f] = val;
            }
            __syncthreads();

#pragma unroll
            for (int kb = 0; kb < KB; kb++) {
                float4 A0 = *(const float4*)&s_v[kb][ib];
                float4 A1 = *(const float4*)&s_v[kb][ib + 4];
                const ull* bp = (const ull*)&s_v[kb][jb];
                ull b20 = bp[0], b21 = bp[1], b22 = bp[2], b23 = bp[3];
                float av[8] = {A0.x, A0.y, A0.z, A0.w, A1.x, A1.y, A1.z, A1.w};
#pragma unroll
                for (int u = 0; u < 8; u++) {
                    ull a2;
                    asm("mov.b64 %0, {%1, %1};" : "=l"(a2) : "f"(av[u]));
                    asm("fma.rn.f32x2 %0, %1, %2, %0;" : "+l"(acc2[u * 4 + 0]) : "l"(a2), "l"(b20));
                    asm("fma.rn.f32x2 %0, %1, %2, %0;" : "+l"(acc2[u * 4 + 1]) : "l"(a2), "l"(b21));
                    asm("fma.rn.f32x2 %0, %1, %2, %0;" : "+l"(acc2[u * 4 + 2]) : "l"(a2), "l"(b22));
                    asm("fma.rn.f32x2 %0, %1, %2, %0;" : "+l"(acc2[u * 4 + 3]) : "l"(a2), "l"(b23));
                }
            }
            __syncthreads();
        }
    }

    float* out = &g_part[blk * NFEAT * NFEAT];
#pragma unroll
    for (int u = 0; u < 8; u++) {
        ull* orow = (ull*)&out[(ib + u) * NFEAT + jb];
#pragma unroll
        for (int vp = 0; vp < 4; vp++) orow[vp] = acc2[u * 4 + vp];
    }
}

// ---- K3b: mgram partials: -B * sum_a m_a m_a^T (+ B^2/2 g g^T in blk 0) -----
__global__ void __launch_bounds__(256) k_mgram(const float* __restrict__ emb) {
    const int blk = blockIdx.x;      // 0..63, 8 a-values each
    const int a0 = blk * 8;

    __shared__ float s_mv[8][NFEAT];
    __shared__ float s_gg[NFEAT];

    const int tid = threadIdx.x;
    const int ty = tid >> 4, tx = tid & 15;
    const int ib = ty * 8, jb = tx * 8;

#pragma unroll
    for (int t = 0; t < 4; t++) {
        int e = tid + t * 256;
        int k = e >> 7, f = e & 127;
        s_mv[k][f] = g_m[(a0 + k) * NFEAT + f];
    }
    if (tid < NFEAT) s_gg[tid] = g_g[tid];
    __syncthreads();

    float acc[8][8];
#pragma unroll
    for (int u = 0; u < 8; u++)
#pragma unroll
        for (int v = 0; v < 8; v++) acc[u][v] = 0.f;

#pragma unroll
    for (int k = 0; k < 8; k++) {
        float4 A0 = *(const float4*)&s_mv[k][ib];
        float4 A1 = *(const float4*)&s_mv[k][ib + 4];
        float4 B0 = *(const float4*)&s_mv[k][jb];
        float4 B1 = *(const float4*)&s_mv[k][jb + 4];
        float av[8] = {A0.x, A0.y, A0.z, A0.w, A1.x, A1.y, A1.z, A1.w};
        float bv[8] = {B0.x, B0.y, B0.z, B0.w, B1.x, B1.y, B1.z, B1.w};
#pragma unroll
        for (int u = 0; u < 8; u++)
#pragma unroll
            for (int v = 0; v < 8; v++) acc[u][v] += av[u] * bv[v];
    }

    const float Bf = (float)BATCH;
    float* out = &g_part[(NGRAM + blk) * NFEAT * NFEAT];
#pragma unroll
    for (int u = 0; u < 8; u++)
#pragma unroll
        for (int v = 0; v < 8; v++) {
            float val = -Bf * acc[u][v];
            if (blk == 0)
                val += 0.5f * Bf * Bf * s_gg[ib + u] * s_gg[jb + v];
            out[(ib + u) * NFEAT + (jb + v)] = val;
        }
    (void)emb;
}

// ---- K4: 4-way split-K partial reduction ------------------------------------
__global__ void k_reduce(const float* __restrict__ emb) {
    int idx = blockIdx.x * blockDim.x + threadIdx.x;  // 0..16383
    int ks = blockIdx.y;                              // 0..3
    float s = 0.f;
#pragma unroll 8
    for (int k = ks * 48; k < (ks + 1) * 48; k++)
        s += g_part[k * NFEAT * NFEAT + idx];
    g_S4[ks * NFEAT * NFEAT + idx] = s;
    (void)emb;
}

// ---- K5: triplet loss partials (int32, with int64 sniff) --------------------
__global__ void k_triplet(const float* __restrict__ emb,
                          const int* __restrict__ trip32) {
    __shared__ float red[256];
    int tid = threadIdx.x;

    bool is64 = (trip32[1] == 0) && (trip32[3] == 0) &&
                (trip32[5] == 0) && (trip32[7] == 0) &&
                ((trip32[0] | trip32[2] | trip32[4] | trip32[6]) != 0);

    int t = blockIdx.x * 256 + tid;
    float s = 0.f;
    if (t < NTRIP) {
        int p, q, r;
        if (is64) {
            p = trip32[(3 * t + 0) * 2];
            q = trip32[(3 * t + 1) * 2];
            r = trip32[(3 * t + 2) * 2];
        } else {
            p = trip32[3 * t + 0];
            q = trip32[3 * t + 1];
            r = trip32[3 * t + 2];
        }
        const float* pp = &emb[p * NFEAT];
        const float* pq = &emb[q * NFEAT];
        const float* pr = &emb[r * NFEAT];
        float ap = 0.f, an = 0.f;
#pragma unroll 8
        for (int f = 0; f < NFEAT; f++) {
            float pv = pp[f];
            float d1 = pv - pq[f]; ap += d1 * d1;
            float d2 = pv - pr[f]; an += d2 * d2;
        }
        float l = ap - an + 1.0f;  // MARGIN
        s = (l > 0.f) ? l : 0.f;
    }
    red[tid] = s;
    __syncthreads();
    for (int o = 128; o > 0; o >>= 1) {
        if (tid < o) red[tid] += red[tid + o];
        __syncthreads();
    }
    if (tid == 0) g_tpart[blockIdx.x] = red[0];
}

// ---- K6: epilogue: S' = 2*sum(g_S4); corr mean + triplet --------------------
__global__ void k_final(const float* __restrict__ emb, float* __restrict__ out) {
    __shared__ float q[NFEAT];
    __shared__ float red[256];
    int tid = threadIdx.x;
    const int NN = NFEAT * NFEAT;
    if (tid < NFEAT) {
        int d = tid * NFEAT + tid;
        float s = 2.f * (g_S4[d] + g_S4[NN + d] + g_S4[2 * NN + d] + g_S4[3 * NN + d]);
        q[tid] = sqrtf(sqrtf(fmaxf(s, 0.f)));
    }
    __syncthreads();

    float s = 0.f;
    for (int p = tid; p < NPAIR; p += 256) {
        int off = p, i = 0;
        while (off >= 127 - i) { off -= 127 - i; i++; }
        int j = i + 1 + off;
        int d = i * NFEAT + j;
        float sij = 2.f * (g_S4[d] + g_S4[NN + d] + g_S4[2 * NN + d] + g_S4[3 * NN + d]);
        s += sqrtf(fmaxf(sij, 0.f)) / (q[i] * q[j]);
    }
    red[tid] = s;
    __syncthreads();
    for (int o = 128; o > 0; o >>= 1) {
        if (tid < o) red[tid] += red[tid + o];
        __syncthreads();
    }
    if (tid == 0) {
        float tl = 0.f;
        for (int k = 0; k < NTBLK; k++) tl += g_tpart[k];
        out[0] = tl * (1.f / NTRIP) + red[0] * (1.f / NPAIR);
    }
    (void)emb;
}

// ---- launch -----------------------------------------------------------------
extern "C" void kernel_launch(void* const* d_in, const int* in_sizes, int n_in,
                              void* d_out, int out_size) {
    const float* emb = (const float*)d_in[0];
    const int* trip = (const int*)d_in[1];
    float* out = (float*)d_out;

    k_means<<<NFEAT, NFEAT>>>(emb);
    k_g<<<1, NFEAT>>>(emb);
    k_gram<<<NGRAM, 256>>>(emb);
    k_mgram<<<NMG, 256>>>(emb);
    dim3 rg(64, 4);
    k_reduce<<<rg, 256>>>(emb);
    k_triplet<<<NTBLK, 256>>>(emb, trip);
    k_final<<<1, 256>>>(emb, out);
}

// round 7
// speedup vs baseline: 1.4238x; 1.4238x over previous
#include <cuda_runtime.h>
#include <math.h>
#include <stdint.h>

#define BATCH 512
#define NFEAT 128
#define NTRIP 1024
#define NGRAM 128            // MMA gram blocks (4 antithetic a-values each)
#define NMG 128              // mgram blocks (4 a-values each)
#define NPART (NGRAM + NMG)  // 256 partial slots
#define NTBLK 4
#define NPAIR 8128
#define VSTRIDE 36           // smem col stride: (4f+k)%32 conflict-free

// ---------------- device scratch ---------------------------------------------
__device__ float g_m[BATCH * NFEAT];
__device__ float g_g[NFEAT];
__device__ float g_part[NPART * NFEAT * NFEAT];
__device__ float g_S4[4 * NFEAT * NFEAT];
__device__ float g_tpart[NTBLK];

__device__ __forceinline__ uint32_t f2tf32(float v) {
    uint32_t u;
    asm("cvt.rna.tf32.f32 %0, %1;" : "=r"(u) : "f"(v));
    return u;
}
__device__ __forceinline__ void mma_tf32(float* d, const uint32_t* a,
                                         uint32_t b0, uint32_t b1) {
    asm volatile(
        "mma.sync.aligned.m16n8k8.row.col.f32.tf32.tf32.f32 "
        "{%0,%1,%2,%3}, {%4,%5,%6,%7}, {%8,%9}, {%0,%1,%2,%3};"
        : "+f"(d[0]), "+f"(d[1]), "+f"(d[2]), "+f"(d[3])
        : "r"(a[0]), "r"(a[1]), "r"(a[2]), "r"(a[3]), "r"(b0), "r"(b1));
}

// ---- K1: row means, 4 a-values per block ------------------------------------
__global__ void k_means(const float* __restrict__ emb) {
    int blk = blockIdx.x, f = threadIdx.x;
    int a0 = blk * 4;
    float xa0 = emb[(a0 + 0) * NFEAT + f];
    float xa1 = emb[(a0 + 1) * NFEAT + f];
    float xa2 = emb[(a0 + 2) * NFEAT + f];
    float xa3 = emb[(a0 + 3) * NFEAT + f];
    float s0 = 0.f, s1 = 0.f, s2 = 0.f, s3 = 0.f;
#pragma unroll 4
    for (int b = 0; b < BATCH; b++) {
        float v = emb[b * NFEAT + f];
        s0 += fabsf(xa0 - v);
        s1 += fabsf(xa1 - v);
        s2 += fabsf(xa2 - v);
        s3 += fabsf(xa3 - v);
    }
    g_m[(a0 + 0) * NFEAT + f] = s0 * (1.f / BATCH);
    g_m[(a0 + 1) * NFEAT + f] = s1 * (1.f / BATCH);
    g_m[(a0 + 2) * NFEAT + f] = s2 * (1.f / BATCH);
    g_m[(a0 + 3) * NFEAT + f] = s3 * (1.f / BATCH);
}

// ---- K2: g[f] = mean_a m[a][f] ---------------------------------------------
__global__ void k_g(const float* __restrict__ emb) {
    int f = threadIdx.x;
    float s = 0.f;
#pragma unroll 8
    for (int a = 0; a < BATCH; a++) s += g_m[a * NFEAT + f];
    g_g[f] = s * (1.f / BATCH);
    (void)emb;
}

// ---- K3: mma.sync tf32 Gram over generated |dx| columns ---------------------
// Block k: a in {2k,2k+1,510-2k,511-2k}, columns b>a, tiles of 32 columns.
// Warp w: rows [ (w&3)*32, +32 ), cols [ (w>>2)*64, +64 ) of the 128x128 tile.
__global__ void __launch_bounds__(256) k_gram(const float* __restrict__ emb) {
    __shared__ uint32_t s_v[NFEAT][VSTRIDE];   // tf32 tile: 128 feat x 32 cols

    const int blk = blockIdx.x;
    const int tid = threadIdx.x;
    const int lane = tid & 31;
    const int w = tid >> 5;
    const int wr = w & 3, wc = w >> 2;
    const int rbase = wr * 32, cbase = wc * 64;

    // gen assignment: column c = lane, features f0..f0+15 (f0 = w*16)
    const int c = lane;
    const int f0 = w * 16;

    float d[2][8][4];
#pragma unroll
    for (int rt = 0; rt < 2; rt++)
#pragma unroll
        for (int j = 0; j < 8; j++)
#pragma unroll
            for (int e = 0; e < 4; e++) d[rt][j][e] = 0.f;

    int alist[4] = {2 * blk, 2 * blk + 1, 510 - 2 * blk, 511 - 2 * blk};

    for (int ai = 0; ai < 4; ai++) {
        const int a = alist[ai];
        const int nb = 511 - a;
        if (nb <= 0) continue;

        // xa regs for this a
        float4 xa[4];
#pragma unroll
        for (int q = 0; q < 4; q++)
            xa[q] = *(const float4*)&emb[a * NFEAT + f0 + q * 4];

        const int ntile = (nb + 31) >> 5;
        // prefetch tile 0
        int b = a + 1 + c;
        bool ok = (b < BATCH);
        float4 rb[4];
        {
            const float4* src = (const float4*)&emb[(ok ? b : (BATCH - 1)) * NFEAT + f0];
#pragma unroll
            for (int q = 0; q < 4; q++) rb[q] = src[q];
        }

        for (int t = 0; t < ntile; t++) {
            __syncthreads();   // prior tile's mma reads complete
            // generate + store tf32 values
#pragma unroll
            for (int q = 0; q < 4; q++) {
                float4 xq = xa[q];
                float4 bq = rb[q];
                float v0 = ok ? fabsf(xq.x - bq.x) : 0.f;
                float v1 = ok ? fabsf(xq.y - bq.y) : 0.f;
                float v2 = ok ? fabsf(xq.z - bq.z) : 0.f;
                float v3 = ok ? fabsf(xq.w - bq.w) : 0.f;
                s_v[f0 + q * 4 + 0][c] = f2tf32(v0);
                s_v[f0 + q * 4 + 1][c] = f2tf32(v1);
                s_v[f0 + q * 4 + 2][c] = f2tf32(v2);
                s_v[f0 + q * 4 + 3][c] = f2tf32(v3);
            }
            __syncthreads();   // tile visible to all warps

            // prefetch next tile (hidden behind mma)
            if (t + 1 < ntile) {
                b = a + 1 + (t + 1) * 32 + c;
                ok = (b < BATCH);
                const float4* src =
                    (const float4*)&emb[(ok ? b : (BATCH - 1)) * NFEAT + f0];
#pragma unroll
                for (int q = 0; q < 4; q++) rb[q] = src[q];
            }

            // mma over the 32-column tile: 4 k-steps of 8
#pragma unroll
            for (int ks = 0; ks < 4; ks++) {
                const int k0 = ks * 8 + (lane & 3);
                const int ar = lane >> 2;
                uint32_t afr[2][4];
#pragma unroll
                for (int rt = 0; rt < 2; rt++) {
                    int rr = rbase + rt * 16 + ar;
                    afr[rt][0] = s_v[rr][k0];
                    afr[rt][1] = s_v[rr + 8][k0];
                    afr[rt][2] = s_v[rr][k0 + 4];
                    afr[rt][3] = s_v[rr + 8][k0 + 4];
                }
#pragma unroll
                for (int j = 0; j < 8; j++) {
                    int bn = cbase + j * 8 + ar;
                    uint32_t b0 = s_v[bn][k0];
                    uint32_t b1 = s_v[bn][k0 + 4];
                    mma_tf32(d[0][j], afr[0], b0, b1);
                    mma_tf32(d[1][j], afr[1], b0, b1);
                }
            }
        }
    }

    // writeout partials
    float* out = &g_part[blk * NFEAT * NFEAT];
    const int gr = lane >> 2, gc = (lane & 3) * 2;
#pragma unroll
    for (int rt = 0; rt < 2; rt++)
#pragma unroll
        for (int j = 0; j < 8; j++) {
            int row = rbase + rt * 16 + gr;
            int col = cbase + j * 8 + gc;
            out[row * NFEAT + col] = d[rt][j][0];
            out[row * NFEAT + col + 1] = d[rt][j][1];
            out[(row + 8) * NFEAT + col] = d[rt][j][2];
            out[(row + 8) * NFEAT + col + 1] = d[rt][j][3];
        }
}

// ---- K3b: mgram partials: -B * sum m m^T (+ B^2/2 gg^T in blk 0) ------------
__global__ void __launch_bounds__(256) k_mgram(const float* __restrict__ emb) {
    const int blk = blockIdx.x;      // 0..127, 4 a-values each
    const int a0 = blk * 4;
    __shared__ float s_mv[4][NFEAT];

    const int tid = threadIdx.x;
    const int ty = tid >> 4, tx = tid & 15;
    const int ib = ty * 8, jb = tx * 8;

#pragma unroll
    for (int t = 0; t < 2; t++) {
        int e = tid + t * 256;
        int k = e >> 7, f = e & 127;
        s_mv[k][f] = g_m[(a0 + k) * NFEAT + f];
    }
    __syncthreads();

    float acc[8][8];
#pragma unroll
    for (int u = 0; u < 8; u++)
#pragma unroll
        for (int v = 0; v < 8; v++) acc[u][v] = 0.f;

#pragma unroll
    for (int k = 0; k < 4; k++) {
        float4 A0 = *(const float4*)&s_mv[k][ib];
        float4 A1 = *(const float4*)&s_mv[k][ib + 4];
        float4 B0 = *(const float4*)&s_mv[k][jb];
        float4 B1 = *(const float4*)&s_mv[k][jb + 4];
        float av[8] = {A0.x, A0.y, A0.z, A0.w, A1.x, A1.y, A1.z, A1.w};
        float bv[8] = {B0.x, B0.y, B0.z, B0.w, B1.x, B1.y, B1.z, B1.w};
#pragma unroll
        for (int u = 0; u < 8; u++)
#pragma unroll
            for (int v = 0; v < 8; v++) acc[u][v] += av[u] * bv[v];
    }

    const float Bf = (float)BATCH;
    float* out = &g_part[(NGRAM + blk) * NFEAT * NFEAT];
#pragma unroll
    for (int u = 0; u < 8; u++)
#pragma unroll
        for (int v = 0; v < 8; v++) {
            float val = -Bf * acc[u][v];
            if (blk == 0)
                val += 0.5f * Bf * Bf * g_g[ib + u] * g_g[jb + v];
            out[(ib + u) * NFEAT + (jb + v)] = val;
        }
    (void)emb;
}

// ---- K4: 4-way split-K partial reduction ------------------------------------
__global__ void k_reduce(const float* __restrict__ emb) {
    int idx = blockIdx.x * blockDim.x + threadIdx.x;  // 0..16383
    int ks = blockIdx.y;                              // 0..3
    float s = 0.f;
#pragma unroll 8
    for (int k = ks * 64; k < (ks + 1) * 64; k++)
        s += g_part[k * NFEAT * NFEAT + idx];
    g_S4[ks * NFEAT * NFEAT + idx] = s;
    (void)emb;
}

// ---- K5: triplet loss partials ----------------------------------------------
__global__ void k_triplet(const float* __restrict__ emb,
                          const int* __restrict__ trip32) {
    __shared__ float red[256];
    int tid = threadIdx.x;
    bool is64 = (trip32[1] == 0) && (trip32[3] == 0) &&
                (trip32[5] == 0) && (trip32[7] == 0) &&
                ((trip32[0] | trip32[2] | trip32[4] | trip32[6]) != 0);
    int t = blockIdx.x * 256 + tid;
    float s = 0.f;
    if (t < NTRIP) {
        int p, q, r;
        if (is64) {
            p = trip32[(3 * t + 0) * 2];
            q = trip32[(3 * t + 1) * 2];
            r = trip32[(3 * t + 2) * 2];
        } else {
            p = trip32[3 * t + 0];
            q = trip32[3 * t + 1];
            r = trip32[3 * t + 2];
        }
        const float* pp = &emb[p * NFEAT];
        const float* pq = &emb[q * NFEAT];
        const float* pr = &emb[r * NFEAT];
        float ap = 0.f, an = 0.f;
#pragma unroll 8
        for (int f = 0; f < NFEAT; f++) {
            float pv = pp[f];
            float d1 = pv - pq[f]; ap += d1 * d1;
            float d2 = pv - pr[f]; an += d2 * d2;
        }
        float lv = ap - an + 1.0f;
        s = (lv > 0.f) ? lv : 0.f;
    }
    red[tid] = s;
    __syncthreads();
    for (int o = 128; o > 0; o >>= 1) {
        if (tid < o) red[tid] += red[tid + o];
        __syncthreads();
    }
    if (tid == 0) g_tpart[blockIdx.x] = red[0];
}

// ---- K6: epilogue -----------------------------------------------------------
__global__ void k_final(const float* __restrict__ emb, float* __restrict__ out) {
    __shared__ float q[NFEAT];
    __shared__ float red[256];
    int tid = threadIdx.x;
    const int NN = NFEAT * NFEAT;
    if (tid < NFEAT) {
        int d = tid * NFEAT + tid;
        float s = 2.f * (g_S4[d] + g_S4[NN + d] + g_S4[2 * NN + d] + g_S4[3 * NN + d]);
        q[tid] = sqrtf(sqrtf(fmaxf(s, 0.f)));
    }
    __syncthreads();

    float s = 0.f;
    for (int p = tid; p < NPAIR; p += 256) {
        int off = p, i = 0;
        while (off >= 127 - i) { off -= 127 - i; i++; }
        int j = i + 1 + off;
        int d = i * NFEAT + j;
        float sij = 2.f * (g_S4[d] + g_S4[NN + d] + g_S4[2 * NN + d] + g_S4[3 * NN + d]);
        s += sqrtf(fmaxf(sij, 0.f)) / (q[i] * q[j]);
    }
    red[tid] = s;
    __syncthreads();
    for (int o = 128; o > 0; o >>= 1) {
        if (tid < o) red[tid] += red[tid + o];
        __syncthreads();
    }
    if (tid == 0) {
        float tl = 0.f;
        for (int k = 0; k < NTBLK; k++) tl += g_tpart[k];
        out[0] = tl * (1.f / NTRIP) + red[0] * (1.f / NPAIR);
    }
    (void)emb;
}

// ---- launch (k_gram 5th so ncu -s 5 profiles it) ----------------------------
extern "C" void kernel_launch(void* const* d_in, const int* in_sizes, int n_in,
                              void* d_out, int out_size) {
    const float* emb = (const float*)d_in[0];
    const int* trip = (const int*)d_in[1];
    float* out = (float*)d_out;

    k_means<<<NFEAT, NFEAT>>>(emb);
    k_g<<<1, NFEAT>>>(emb);
    k_triplet<<<NTBLK, 256>>>(emb, trip);
    k_mgram<<<NMG, 256>>>(emb);
    k_gram<<<NGRAM, 256>>>(emb);
    dim3 rg(64, 4);
    k_reduce<<<rg, 256>>>(emb);
    k_final<<<1, 256>>>(emb, out);
}

// round 9
// speedup vs baseline: 1.5297x; 1.0744x over previous
#include <cuda_runtime.h>
#include <math.h>
#include <stdint.h>

#define BATCH 512
#define NFEAT 128
#define NTRIP 1024
#define NGRAM 128            // gram blocks (4 antithetic a-values each)
#define NTBLK 4
#define NPAIR 8128
#define VSTRIDE 36           // smem col stride: (4f+k)%32 conflict-free

// ---------------- device scratch ---------------------------------------------
__device__ float g_m[BATCH * NFEAT];
__device__ float g_g[NFEAT];
__device__ float g_part[NGRAM * NFEAT * NFEAT];
__device__ float g_S4[4 * NFEAT * NFEAT];
__device__ float g_tpart[NTBLK];

__device__ __forceinline__ uint32_t f2tf32(float v) {
    uint32_t u;
    asm("cvt.rna.tf32.f32 %0, %1;" : "=r"(u) : "f"(v));
    return u;
}
__device__ __forceinline__ void mma_tf32(float* d, const uint32_t* a,
                                         uint32_t b0, uint32_t b1) {
    asm volatile(
        "mma.sync.aligned.m16n8k8.row.col.f32.tf32.tf32.f32 "
        "{%0,%1,%2,%3}, {%4,%5,%6,%7}, {%8,%9}, {%0,%1,%2,%3};"
        : "+f"(d[0]), "+f"(d[1]), "+f"(d[2]), "+f"(d[3])
        : "r"(a[0]), "r"(a[1]), "r"(a[2]), "r"(a[3]), "r"(b0), "r"(b1));
}

// ---- K1: row means, 4 a-values per block ------------------------------------
__global__ void k_means(const float* __restrict__ emb) {
    int blk = blockIdx.x, f = threadIdx.x;
    int a0 = blk * 4;
    float xa0 = emb[(a0 + 0) * NFEAT + f];
    float xa1 = emb[(a0 + 1) * NFEAT + f];
    float xa2 = emb[(a0 + 2) * NFEAT + f];
    float xa3 = emb[(a0 + 3) * NFEAT + f];
    float s0 = 0.f, s1 = 0.f, s2 = 0.f, s3 = 0.f;
#pragma unroll 4
    for (int b = 0; b < BATCH; b++) {
        float v = emb[b * NFEAT + f];
        s0 += fabsf(xa0 - v);
        s1 += fabsf(xa1 - v);
        s2 += fabsf(xa2 - v);
        s3 += fabsf(xa3 - v);
    }
    g_m[(a0 + 0) * NFEAT + f] = s0 * (1.f / BATCH);
    g_m[(a0 + 1) * NFEAT + f] = s1 * (1.f / BATCH);
    g_m[(a0 + 2) * NFEAT + f] = s2 * (1.f / BATCH);
    g_m[(a0 + 3) * NFEAT + f] = s3 * (1.f / BATCH);
}

// ---- K2: g[f] = mean_a m[a][f] ---------------------------------------------
__global__ void k_g(const float* __restrict__ emb) {
    int f = threadIdx.x;
    float s = 0.f;
#pragma unroll 8
    for (int a = 0; a < BATCH; a++) s += g_m[a * NFEAT + f];
    g_g[f] = s * (1.f / BATCH);
    (void)emb;
}

// ---- K3: mma.sync tf32 Gram + fused fp32 mean-centering epilogue ------------
// Block k: a in {2k,2k+1,510-2k,511-2k}, |dx| columns b>a, tiles of 32.
// Warp w: rows [(w&3)*32,+32), cols [(w>>2)*64,+64) of the 128x128 tile.
// partial_blk = T'_blk - B*sum_{a in blk} m_a m_a^T  (+ blk0: 0.5*B^2*gg^T)
__global__ void __launch_bounds__(256) k_gram(const float* __restrict__ emb) {
    __shared__ uint32_t s_v[NFEAT][VSTRIDE];   // tf32 tile: 128 feat x 32 cols
    __shared__ float s_m[4][NFEAT];            // m rows for epilogue
    __shared__ float s_gg[NFEAT];

    const int blk = blockIdx.x;
    const int tid = threadIdx.x;
    const int lane = tid & 31;
    const int w = tid >> 5;
    const int wr = w & 3, wc = w >> 2;
    const int rbase = wr * 32, cbase = wc * 64;

    const int c = lane;        // generated column
    const int f0 = w * 16;     // feature span for gen

    float d[2][8][4];
#pragma unroll
    for (int rt = 0; rt < 2; rt++)
#pragma unroll
        for (int j = 0; j < 8; j++)
#pragma unroll
            for (int e = 0; e < 4; e++) d[rt][j][e] = 0.f;

    int alist[4] = {2 * blk, 2 * blk + 1, 510 - 2 * blk, 511 - 2 * blk};

    for (int ai = 0; ai < 4; ai++) {
        const int a = alist[ai];
        const int nb = 511 - a;
        if (nb <= 0) continue;

        float4 xa[4];
#pragma unroll
        for (int q = 0; q < 4; q++)
            xa[q] = *(const float4*)&emb[a * NFEAT + f0 + q * 4];

        const int ntile = (nb + 31) >> 5;
        int b = a + 1 + c;
        bool ok = (b < BATCH);
        float4 rb[4];
        {
            const float4* src = (const float4*)&emb[(ok ? b : (BATCH - 1)) * NFEAT + f0];
#pragma unroll
            for (int q = 0; q < 4; q++) rb[q] = src[q];
        }

        for (int t = 0; t < ntile; t++) {
            __syncthreads();
#pragma unroll
            for (int q = 0; q < 4; q++) {
                float4 xq = xa[q];
                float4 bq = rb[q];
                float v0 = ok ? fabsf(xq.x - bq.x) : 0.f;
                float v1 = ok ? fabsf(xq.y - bq.y) : 0.f;
                float v2 = ok ? fabsf(xq.z - bq.z) : 0.f;
                float v3 = ok ? fabsf(xq.w - bq.w) : 0.f;
                s_v[f0 + q * 4 + 0][c] = f2tf32(v0);
                s_v[f0 + q * 4 + 1][c] = f2tf32(v1);
                s_v[f0 + q * 4 + 2][c] = f2tf32(v2);
                s_v[f0 + q * 4 + 3][c] = f2tf32(v3);
            }
            __syncthreads();

            if (t + 1 < ntile) {
                b = a + 1 + (t + 1) * 32 + c;
                ok = (b < BATCH);
                const float4* src =
                    (const float4*)&emb[(ok ? b : (BATCH - 1)) * NFEAT + f0];
#pragma unroll
                for (int q = 0; q < 4; q++) rb[q] = src[q];
            }

#pragma unroll
            for (int ks = 0; ks < 4; ks++) {
                const int k0 = ks * 8 + (lane & 3);
                const int ar = lane >> 2;
                uint32_t afr[2][4];
#pragma unroll
                for (int rt = 0; rt < 2; rt++) {
                    int rr = rbase + rt * 16 + ar;
                    afr[rt][0] = s_v[rr][k0];
                    afr[rt][1] = s_v[rr + 8][k0];
                    afr[rt][2] = s_v[rr][k0 + 4];
                    afr[rt][3] = s_v[rr + 8][k0 + 4];
                }
#pragma unroll
                for (int j = 0; j < 8; j++) {
                    int bn = cbase + j * 8 + ar;
                    uint32_t b0 = s_v[bn][k0];
                    uint32_t b1 = s_v[bn][k0 + 4];
                    mma_tf32(d[0][j], afr[0], b0, b1);
                    mma_tf32(d[1][j], afr[1], b0, b1);
                }
            }
        }
    }

    // ---- fp32 epilogue: -B * sum_a m_a m_a^T (+ blk0: +0.5*B^2*gg^T) --------
    __syncthreads();
#pragma unroll
    for (int t = 0; t < 2; t++) {
        int e = tid + t * 256;
        int aa = e >> 7, f = e & 127;
        s_m[aa][f] = g_m[alist[aa] * NFEAT + f];
    }
    if (tid < NFEAT) s_gg[tid] = g_g[tid];
    __syncthreads();

    const int gr = lane >> 2, gc = (lane & 3) * 2;
    const float Bf = (float)BATCH;
#pragma unroll
    for (int aa = 0; aa < 4; aa++) {
        float am[4];
#pragma unroll
        for (int rt = 0; rt < 2; rt++) {
            am[rt * 2 + 0] = s_m[aa][rbase + rt * 16 + gr];
            am[rt * 2 + 1] = s_m[aa][rbase + rt * 16 + gr + 8];
        }
#pragma unroll
        for (int j = 0; j < 8; j++) {
            float bm0 = s_m[aa][cbase + j * 8 + gc];
            float bm1 = s_m[aa][cbase + j * 8 + gc + 1];
#pragma unroll
            for (int rt = 0; rt < 2; rt++) {
                d[rt][j][0] -= Bf * am[rt * 2 + 0] * bm0;
                d[rt][j][1] -= Bf * am[rt * 2 + 0] * bm1;
                d[rt][j][2] -= Bf * am[rt * 2 + 1] * bm0;
                d[rt][j][3] -= Bf * am[rt * 2 + 1] * bm1;
            }
        }
    }
    if (blk == 0) {
        const float hB2 = 0.5f * Bf * Bf;
        float gm[4];
#pragma unroll
        for (int rt = 0; rt < 2; rt++) {
            gm[rt * 2 + 0] = s_gg[rbase + rt * 16 + gr];
            gm[rt * 2 + 1] = s_gg[rbase + rt * 16 + gr + 8];
        }
#pragma unroll
        for (int j = 0; j < 8; j++) {
            float gb0 = s_gg[cbase + j * 8 + gc];
            float gb1 = s_gg[cbase + j * 8 + gc + 1];
#pragma unroll
            for (int rt = 0; rt < 2; rt++) {
                d[rt][j][0] += hB2 * gm[rt * 2 + 0] * gb0;
                d[rt][j][1] += hB2 * gm[rt * 2 + 0] * gb1;
                d[rt][j][2] += hB2 * gm[rt * 2 + 1] * gb0;
                d[rt][j][3] += hB2 * gm[rt * 2 + 1] * gb1;
            }
        }
    }

    // writeout partials
    float* out = &g_part[blk * NFEAT * NFEAT];
#pragma unroll
    for (int rt = 0; rt < 2; rt++)
#pragma unroll
        for (int j = 0; j < 8; j++) {
            int row = rbase + rt * 16 + gr;
            int col = cbase + j * 8 + gc;
            out[row * NFEAT + col] = d[rt][j][0];
            out[row * NFEAT + col + 1] = d[rt][j][1];
            out[(row + 8) * NFEAT + col] = d[rt][j][2];
            out[(row + 8) * NFEAT + col + 1] = d[rt][j][3];
        }
}

// ---- K4: 4-way split-K partial reduction (128 slabs) ------------------------
__global__ void k_reduce(const float* __restrict__ emb) {
    int idx = blockIdx.x * blockDim.x + threadIdx.x;  // 0..16383
    int ks = blockIdx.y;                              // 0..3
    float s = 0.f;
#pragma unroll 8
    for (int k = ks * 32; k < (ks + 1) * 32; k++)
        s += g_part[k * NFEAT * NFEAT + idx];
    g_S4[ks * NFEAT * NFEAT + idx] = s;
    (void)emb;
}

// ---- K5: triplet loss partials ----------------------------------------------
__global__ void k_triplet(const float* __restrict__ emb,
                          const int* __restrict__ trip32) {
    __shared__ float red[256];
    int tid = threadIdx.x;
    bool is64 = (trip32[1] == 0) && (trip32[3] == 0) &&
                (trip32[5] == 0) && (trip32[7] == 0) &&
                ((trip32[0] | trip32[2] | trip32[4] | trip32[6]) != 0);
    int t = blockIdx.x * 256 + tid;
    float s = 0.f;
    if (t < NTRIP) {
        int p, q, r;
        if (is64) {
            p = trip32[(3 * t + 0) * 2];
            q = trip32[(3 * t + 1) * 2];
            r = trip32[(3 * t + 2) * 2];
        } else {
            p = trip32[3 * t + 0];
            q = trip32[3 * t + 1];
            r = trip32[3 * t + 2];
        }
        const float* pp = &emb[p * NFEAT];
        const float* pq = &emb[q * NFEAT];
        const float* pr = &emb[r * NFEAT];
        float ap = 0.f, an = 0.f;
#pragma unroll 8
        for (int f = 0; f < NFEAT; f++) {
            float pv = pp[f];
            float d1 = pv - pq[f]; ap += d1 * d1;
            float d2 = pv - pr[f]; an += d2 * d2;
        }
        float lv = ap - an + 1.0f;
        s = (lv > 0.f) ? lv : 0.f;
    }
    red[tid] = s;
    __syncthreads();
    for (int o = 128; o > 0; o >>= 1) {
        if (tid < o) red[tid] += red[tid + o];
        __syncthreads();
    }
    if (tid == 0) g_tpart[blockIdx.x] = red[0];
}

// ---- K6: epilogue -----------------------------------------------------------
__global__ void k_final(const float* __restrict__ emb, float* __restrict__ out) {
    __shared__ float q[NFEAT];
    __shared__ float red[256];
    int tid = threadIdx.x;
    const int NN = NFEAT * NFEAT;
    if (tid < NFEAT) {
        int d = tid * NFEAT + tid;
        float s = 2.f * (g_S4[d] + g_S4[NN + d] + g_S4[2 * NN + d] + g_S4[3 * NN + d]);
        q[tid] = sqrtf(sqrtf(fmaxf(s, 0.f)));
    }
    __syncthreads();

    float s = 0.f;
    for (int p = tid; p < NPAIR; p += 256) {
        int off = p, i = 0;
        while (off >= 127 - i) { off -= 127 - i; i++; }
        int j = i + 1 + off;
        int d = i * NFEAT + j;
        float sij = 2.f * (g_S4[d] + g_S4[NN + d] + g_S4[2 * NN + d] + g_S4[3 * NN + d]);
        s += sqrtf(fmaxf(sij, 0.f)) / (q[i] * q[j]);
    }
    red[tid] = s;
    __syncthreads();
    for (int o = 128; o > 0; o >>= 1) {
        if (tid < o) red[tid] += red[tid + o];
        __syncthreads();
    }
    if (tid == 0) {
        float tl = 0.f;
        for (int k = 0; k < NTBLK; k++) tl += g_tpart[k];
        out[0] = tl * (1.f / NTRIP) + red[0] * (1.f / NPAIR);
    }
    (void)emb;
}

// ---- launch (k_gram 4th: ncu captures the 4th launch) -----------------------
extern "C" void kernel_launch(void* const* d_in, const int* in_sizes, int n_in,
                              void* d_out, int out_size) {
    const float* emb = (const float*)d_in[0];
    const int* trip = (const int*)d_in[1];
    float* out = (float*)d_out;

    k_means<<<NFEAT, NFEAT>>>(emb);
    k_g<<<1, NFEAT>>>(emb);
    k_triplet<<<NTBLK, 256>>>(emb, trip);
    k_gram<<<NGRAM, 256>>>(emb);
    dim3 rg(64, 4);
    k_reduce<<<rg, 256>>>(emb);
    k_final<<<1, 256>>>(emb, out);
}

// round 10
// speedup vs baseline: 2.1903x; 1.4319x over previous
#include <cuda_runtime.h>
#include <math.h>
#include <stdint.h>

#define BATCH 512
#define NFEAT 128
#define NTRIP 1024
#define NGRAM 256            // gram blocks (2 antithetic a-values each)
#define NTBLK 4
#define NPAIR 8128
#define VSTRIDE 36           // smem col stride: (4f+k)%32 conflict-free
#define NRED1 16             // stage-1 reduction slices

// ---------------- device scratch ---------------------------------------------
__device__ float g_m[BATCH * NFEAT];
__device__ float g_gp[8][NFEAT];                 // partial column sums of m
__device__ float g_part[NGRAM * NFEAT * NFEAT];  // 16 MB split-K partials
__device__ float g_Sr[NRED1 * NFEAT * NFEAT];    // stage-1 sums
__device__ float g_S[NFEAT * NFEAT];             // final S'/2
__device__ float g_tpart[NTBLK];

__device__ __forceinline__ uint32_t f2tf32(float v) {
    uint32_t u;
    asm("cvt.rna.tf32.f32 %0, %1;" : "=r"(u) : "f"(v));
    return u;
}
__device__ __forceinline__ void mma_tf32(float* d, const uint32_t* a,
                                         uint32_t b0, uint32_t b1) {
    asm volatile(
        "mma.sync.aligned.m16n8k8.row.col.f32.tf32.tf32.f32 "
        "{%0,%1,%2,%3}, {%4,%5,%6,%7}, {%8,%9}, {%0,%1,%2,%3};"
        : "+f"(d[0]), "+f"(d[1]), "+f"(d[2]), "+f"(d[3])
        : "r"(a[0]), "r"(a[1]), "r"(a[2]), "r"(a[3]), "r"(b0), "r"(b1));
}

// ---- K1: row means; 512 threads = 128 f x 4 b-quarters ----------------------
__global__ void __launch_bounds__(512) k_means(const float* __restrict__ emb) {
    __shared__ float s_red[4][4][NFEAT];   // [h][a][f]
    int tid = threadIdx.x;
    int f = tid & 127, h = tid >> 7;
    int a0 = blockIdx.x * 4;
    float xa0 = emb[(a0 + 0) * NFEAT + f];
    float xa1 = emb[(a0 + 1) * NFEAT + f];
    float xa2 = emb[(a0 + 2) * NFEAT + f];
    float xa3 = emb[(a0 + 3) * NFEAT + f];
    float s0 = 0.f, s1 = 0.f, s2 = 0.f, s3 = 0.f;
    int bbase = h * 128;
    for (int b0 = 0; b0 < 128; b0 += 8) {
        float v[8];
#pragma unroll
        for (int u = 0; u < 8; u++) v[u] = emb[(bbase + b0 + u) * NFEAT + f];
#pragma unroll
        for (int u = 0; u < 8; u++) {
            s0 += fabsf(xa0 - v[u]);
            s1 += fabsf(xa1 - v[u]);
            s2 += fabsf(xa2 - v[u]);
            s3 += fabsf(xa3 - v[u]);
        }
    }
    s_red[h][0][f] = s0;
    s_red[h][1][f] = s1;
    s_red[h][2][f] = s2;
    s_red[h][3][f] = s3;
    __syncthreads();
    if (h == 0) {
#pragma unroll
        for (int aa = 0; aa < 4; aa++) {
            float s = s_red[0][aa][f] + s_red[1][aa][f] +
                      s_red[2][aa][f] + s_red[3][aa][f];
            g_m[(a0 + aa) * NFEAT + f] = s * (1.f / BATCH);
        }
    }
}

// ---- K2: partial column sums of m (8 blocks x 64 rows) ----------------------
__global__ void k_g(const float* __restrict__ emb) {
    int f = threadIdx.x;
    int p = blockIdx.x;
    float s = 0.f;
#pragma unroll 8
    for (int a = p * 64; a < p * 64 + 64; a++) s += g_m[a * NFEAT + f];
    g_gp[p][f] = s;
    (void)emb;
}

// ---- K3: mma.sync tf32 Gram + fused -B*mm^T epilogue ------------------------
// Block k: a in {k, 511-k} (511 columns total), |dx| columns b>a, tiles of 32.
// Warp w: rows [(w&3)*32,+32), cols [(w>>2)*64,+64) of the 128x128 tile.
__global__ void __launch_bounds__(256, 2) k_gram(const float* __restrict__ emb) {
    __shared__ uint32_t s_v[NFEAT][VSTRIDE];
    __shared__ float s_m[2][NFEAT];

    const int blk = blockIdx.x;
    const int tid = threadIdx.x;
    const int lane = tid & 31;
    const int w = tid >> 5;
    const int wr = w & 3, wc = w >> 2;
    const int rbase = wr * 32, cbase = wc * 64;

    const int c = lane;
    const int f0 = w * 16;

    float d[2][8][4];
#pragma unroll
    for (int rt = 0; rt < 2; rt++)
#pragma unroll
        for (int j = 0; j < 8; j++)
#pragma unroll
            for (int e = 0; e < 4; e++) d[rt][j][e] = 0.f;

    int alist[2] = {blk, 511 - blk};

    for (int ai = 0; ai < 2; ai++) {
        const int a = alist[ai];
        const int nb = 511 - a;
        if (nb <= 0) continue;

        float4 xa[4];
#pragma unroll
        for (int q = 0; q < 4; q++)
            xa[q] = *(const float4*)&emb[a * NFEAT + f0 + q * 4];

        const int ntile = (nb + 31) >> 5;
        int b = a + 1 + c;
        bool ok = (b < BATCH);
        float4 rb[4];
        {
            const float4* src = (const float4*)&emb[(ok ? b : (BATCH - 1)) * NFEAT + f0];
#pragma unroll
            for (int q = 0; q < 4; q++) rb[q] = src[q];
        }

        for (int t = 0; t < ntile; t++) {
            __syncthreads();
#pragma unroll
            for (int q = 0; q < 4; q++) {
                float4 xq = xa[q];
                float4 bq = rb[q];
                float v0 = ok ? fabsf(xq.x - bq.x) : 0.f;
                float v1 = ok ? fabsf(xq.y - bq.y) : 0.f;
                float v2 = ok ? fabsf(xq.z - bq.z) : 0.f;
                float v3 = ok ? fabsf(xq.w - bq.w) : 0.f;
                s_v[f0 + q * 4 + 0][c] = f2tf32(v0);
                s_v[f0 + q * 4 + 1][c] = f2tf32(v1);
                s_v[f0 + q * 4 + 2][c] = f2tf32(v2);
                s_v[f0 + q * 4 + 3][c] = f2tf32(v3);
            }
            __syncthreads();

            if (t + 1 < ntile) {
                b = a + 1 + (t + 1) * 32 + c;
                ok = (b < BATCH);
                const float4* src =
                    (const float4*)&emb[(ok ? b : (BATCH - 1)) * NFEAT + f0];
#pragma unroll
                for (int q = 0; q < 4; q++) rb[q] = src[q];
            }

#pragma unroll
            for (int ks = 0; ks < 4; ks++) {
                const int k0 = ks * 8 + (lane & 3);
                const int ar = lane >> 2;
                uint32_t afr[2][4];
#pragma unroll
                for (int rt = 0; rt < 2; rt++) {
                    int rr = rbase + rt * 16 + ar;
                    afr[rt][0] = s_v[rr][k0];
                    afr[rt][1] = s_v[rr + 8][k0];
                    afr[rt][2] = s_v[rr][k0 + 4];
                    afr[rt][3] = s_v[rr + 8][k0 + 4];
                }
#pragma unroll
                for (int j = 0; j < 8; j++) {
                    int bn = cbase + j * 8 + ar;
                    uint32_t b0 = s_v[bn][k0];
                    uint32_t b1 = s_v[bn][k0 + 4];
                    mma_tf32(d[0][j], afr[0], b0, b1);
                    mma_tf32(d[1][j], afr[1], b0, b1);
                }
            }
        }
    }

    // ---- fp32 epilogue: -B * sum_{a in blk} m_a m_a^T ------------------------
    __syncthreads();
    {
        int aa = tid >> 7, f = tid & 127;
        s_m[aa][f] = g_m[alist[aa] * NFEAT + f];
    }
    __syncthreads();

    const int gr = lane >> 2, gc = (lane & 3) * 2;
    const float Bf = (float)BATCH;
#pragma unroll
    for (int aa = 0; aa < 2; aa++) {
        float am[4];
#pragma unroll
        for (int rt = 0; rt < 2; rt++) {
            am[rt * 2 + 0] = s_m[aa][rbase + rt * 16 + gr];
            am[rt * 2 + 1] = s_m[aa][rbase + rt * 16 + gr + 8];
        }
#pragma unroll
        for (int j = 0; j < 8; j++) {
            float bm0 = s_m[aa][cbase + j * 8 + gc];
            float bm1 = s_m[aa][cbase + j * 8 + gc + 1];
#pragma unroll
            for (int rt = 0; rt < 2; rt++) {
                d[rt][j][0] -= Bf * am[rt * 2 + 0] * bm0;
                d[rt][j][1] -= Bf * am[rt * 2 + 0] * bm1;
                d[rt][j][2] -= Bf * am[rt * 2 + 1] * bm0;
                d[rt][j][3] -= Bf * am[rt * 2 + 1] * bm1;
            }
        }
    }

    float* out = &g_part[blk * NFEAT * NFEAT];
#pragma unroll
    for (int rt = 0; rt < 2; rt++)
#pragma unroll
        for (int j = 0; j < 8; j++) {
            int row = rbase + rt * 16 + gr;
            int col = cbase + j * 8 + gc;
            out[row * NFEAT + col] = d[rt][j][0];
            out[row * NFEAT + col + 1] = d[rt][j][1];
            out[(row + 8) * NFEAT + col] = d[rt][j][2];
            out[(row + 8) * NFEAT + col + 1] = d[rt][j][3];
        }
}

// ---- K4a: reduction stage 1: 16 slices of 16 slabs each ---------------------
__global__ void k_reduce1(const float* __restrict__ emb) {
    int idx = blockIdx.x * blockDim.x + threadIdx.x;  // 0..16383
    int ks = blockIdx.y;                              // 0..15
    float s = 0.f;
#pragma unroll
    for (int k = ks * 16; k < ks * 16 + 16; k++)
        s += g_part[k * NFEAT * NFEAT + idx];
    g_Sr[ks * NFEAT * NFEAT + idx] = s;
    (void)emb;
}

// ---- K4b: reduction stage 2 + 0.5*Msum Msum^T term --------------------------
__global__ void k_reduce2(const float* __restrict__ emb) {
    int idx = blockIdx.x * blockDim.x + threadIdx.x;  // 0..16383
    int i = idx >> 7, j = idx & 127;
    float s = 0.f;
#pragma unroll
    for (int k = 0; k < NRED1; k++)
        s += g_Sr[k * NFEAT * NFEAT + idx];
    float mi = 0.f, mj = 0.f;
#pragma unroll
    for (int p = 0; p < 8; p++) {
        mi += g_gp[p][i];
        mj += g_gp[p][j];
    }
    g_S[idx] = s + 0.5f * mi * mj;
    (void)emb;
}

// ---- K5: triplet loss partials ----------------------------------------------
__global__ void k_triplet(const float* __restrict__ emb,
                          const int* __restrict__ trip32) {
    __shared__ float red[256];
    int tid = threadIdx.x;
    bool is64 = (trip32[1] == 0) && (trip32[3] == 0) &&
                (trip32[5] == 0) && (trip32[7] == 0) &&
                ((trip32[0] | trip32[2] | trip32[4] | trip32[6]) != 0);
    int t = blockIdx.x * 256 + tid;
    float s = 0.f;
    if (t < NTRIP) {
        int p, q, r;
        if (is64) {
            p = trip32[(3 * t + 0) * 2];
            q = trip32[(3 * t + 1) * 2];
            r = trip32[(3 * t + 2) * 2];
        } else {
            p = trip32[3 * t + 0];
            q = trip32[3 * t + 1];
            r = trip32[3 * t + 2];
        }
        const float* pp = &emb[p * NFEAT];
        const float* pq = &emb[q * NFEAT];
        const float* pr = &emb[r * NFEAT];
        float ap = 0.f, an = 0.f;
#pragma unroll 8
        for (int f = 0; f < NFEAT; f++) {
            float pv = pp[f];
            float d1 = pv - pq[f]; ap += d1 * d1;
            float d2 = pv - pr[f]; an += d2 * d2;
        }
        float lv = ap - an + 1.0f;
        s = (lv > 0.f) ? lv : 0.f;
    }
    red[tid] = s;
    __syncthreads();
    for (int o = 128; o > 0; o >>= 1) {
        if (tid < o) red[tid] += red[tid + o];
        __syncthreads();
    }
    if (tid == 0) g_tpart[blockIdx.x] = red[0];
}

// ---- K6: epilogue: corr mean + triplet --------------------------------------
// S'_ij = 2*g_S[ij]; corr = sqrt(S')/ (S'_ii^(1/4) S'_jj^(1/4))
__global__ void k_final(const float* __restrict__ emb, float* __restrict__ out) {
    __shared__ float q[NFEAT];
    __shared__ float red[256];
    int tid = threadIdx.x;
    if (tid < NFEAT)
        q[tid] = sqrtf(sqrtf(fmaxf(2.f * g_S[tid * NFEAT + tid], 0.f)));
    __syncthreads();

    float s = 0.f;
    int p0 = tid * 32;
    if (p0 < NPAIR) {
        // closed-form start index: i = floor((255 - sqrt(255^2 - 8p))/2)
        float disc = 65025.f - 8.f * (float)p0;
        int i = (int)((255.f - sqrtf(disc)) * 0.5f);
        if (i < 0) i = 0;
        // fix potential fp off-by-one: cum(i) = 127i - i(i-1)/2
        while (i > 0 && (127 * i - (i * (i - 1)) / 2) > p0) i--;
        while ((127 * (i + 1) - ((i + 1) * i) / 2) <= p0) i++;
        int j = i + 1 + (p0 - (127 * i - (i * (i - 1)) / 2));
        int pend = p0 + 32;
        if (pend > NPAIR) pend = NPAIR;
        for (int p = p0; p < pend; p++) {
            float sij = 2.f * g_S[i * NFEAT + j];
            s += sqrtf(fmaxf(sij, 0.f)) / (q[i] * q[j]);
            if (++j >= NFEAT) { i++; j = i + 1; }
        }
    }
    red[tid] = s;
    __syncthreads();
    for (int o = 128; o > 0; o >>= 1) {
        if (tid < o) red[tid] += red[tid + o];
        __syncthreads();
    }
    if (tid == 0) {
        float tl = 0.f;
        for (int k = 0; k < NTBLK; k++) tl += g_tpart[k];
        out[0] = tl * (1.f / NTRIP) + red[0] * (1.f / NPAIR);
    }
    (void)emb;
}

// ---- launch (k_gram 4th: ncu captures the 4th launch) -----------------------
extern "C" void kernel_launch(void* const* d_in, const int* in_sizes, int n_in,
                              void* d_out, int out_size) {
    const float* emb = (const float*)d_in[0];
    const int* trip = (const int*)d_in[1];
    float* out = (float*)d_out;

    k_means<<<NFEAT, 512>>>(emb);
    k_g<<<8, NFEAT>>>(emb);
    k_triplet<<<NTBLK, 256>>>(emb, trip);
    k_gram<<<NGRAM, 256>>>(emb);
    dim3 r1(64, NRED1);
    k_reduce1<<<r1, 256>>>(emb);
    k_reduce2<<<64, 256>>>(emb);
    k_final<<<1, 256>>>(emb, out);
}

// round 11
// speedup vs baseline: 2.3728x; 1.0833x over previous
#include <cuda_runtime.h>
#include <math.h>
#include <stdint.h>

#define BATCH 512
#define NFEAT 128
#define NTRIP 1024
#define NGRAM 256            // gram blocks (2 antithetic a-values each)
#define NTBLK 4
#define NPAIR 8128
#define VSTRIDE 36           // smem col stride: (4f+k)%32 conflict-free
#define NRED1 16             // stage-1 reduction slices

// ---------------- device scratch ---------------------------------------------
__device__ float g_m[BATCH * NFEAT];
__device__ float g_gp[8][NFEAT];                 // partial column sums of m
__device__ float g_part[NGRAM * NFEAT * NFEAT];  // split-K partials (upper tiles)
__device__ float g_Sr[NRED1 * NFEAT * NFEAT];    // stage-1 sums
__device__ float g_S[NFEAT * NFEAT];             // final S'/2 (upper valid)
__device__ float g_tpart[NTBLK];

__device__ __forceinline__ uint32_t f2tf32(float v) {
    uint32_t u;
    asm("cvt.rna.tf32.f32 %0, %1;" : "=r"(u) : "f"(v));
    return u;
}
__device__ __forceinline__ void mma_tf32(float* d, const uint32_t* a,
                                         uint32_t b0, uint32_t b1) {
    asm volatile(
        "mma.sync.aligned.m16n8k8.row.col.f32.tf32.tf32.f32 "
        "{%0,%1,%2,%3}, {%4,%5,%6,%7}, {%8,%9}, {%0,%1,%2,%3};"
        : "+f"(d[0]), "+f"(d[1]), "+f"(d[2]), "+f"(d[3])
        : "r"(a[0]), "r"(a[1]), "r"(a[2]), "r"(a[3]), "r"(b0), "r"(b1));
}

// ---- K1: row means; 512 threads = 128 f x 4 b-quarters ----------------------
__global__ void __launch_bounds__(512) k_means(const float* __restrict__ emb) {
    __shared__ float s_red[4][4][NFEAT];   // [h][a][f]
    int tid = threadIdx.x;
    int f = tid & 127, h = tid >> 7;
    int a0 = blockIdx.x * 4;
    float xa0 = emb[(a0 + 0) * NFEAT + f];
    float xa1 = emb[(a0 + 1) * NFEAT + f];
    float xa2 = emb[(a0 + 2) * NFEAT + f];
    float xa3 = emb[(a0 + 3) * NFEAT + f];
    float s0 = 0.f, s1 = 0.f, s2 = 0.f, s3 = 0.f;
    int bbase = h * 128;
    for (int b0 = 0; b0 < 128; b0 += 8) {
        float v[8];
#pragma unroll
        for (int u = 0; u < 8; u++) v[u] = emb[(bbase + b0 + u) * NFEAT + f];
#pragma unroll
        for (int u = 0; u < 8; u++) {
            s0 += fabsf(xa0 - v[u]);
            s1 += fabsf(xa1 - v[u]);
            s2 += fabsf(xa2 - v[u]);
            s3 += fabsf(xa3 - v[u]);
        }
    }
    s_red[h][0][f] = s0;
    s_red[h][1][f] = s1;
    s_red[h][2][f] = s2;
    s_red[h][3][f] = s3;
    __syncthreads();
    if (h == 0) {
#pragma unroll
        for (int aa = 0; aa < 4; aa++) {
            float s = s_red[0][aa][f] + s_red[1][aa][f] +
                      s_red[2][aa][f] + s_red[3][aa][f];
            g_m[(a0 + aa) * NFEAT + f] = s * (1.f / BATCH);
        }
    }
}

// ---- K2 (fused aux): blocks 0-7: column partial sums of m; 8-11: triplets ---
__global__ void __launch_bounds__(256) k_aux(const float* __restrict__ emb,
                                             const int* __restrict__ trip32) {
    int bid = blockIdx.x;
    int tid = threadIdx.x;
    if (bid < 8) {
        if (tid < NFEAT) {
            int f = tid;
            float s = 0.f;
#pragma unroll 8
            for (int a = bid * 64; a < bid * 64 + 64; a++)
                s += g_m[a * NFEAT + f];
            g_gp[bid][f] = s;
        }
        return;
    }
    // triplet blocks
    __shared__ float red[256];
    bool is64 = (trip32[1] == 0) && (trip32[3] == 0) &&
                (trip32[5] == 0) && (trip32[7] == 0) &&
                ((trip32[0] | trip32[2] | trip32[4] | trip32[6]) != 0);
    int t = (bid - 8) * 256 + tid;
    float s = 0.f;
    if (t < NTRIP) {
        int p, q, r;
        if (is64) {
            p = trip32[(3 * t + 0) * 2];
            q = trip32[(3 * t + 1) * 2];
            r = trip32[(3 * t + 2) * 2];
        } else {
            p = trip32[3 * t + 0];
            q = trip32[3 * t + 1];
            r = trip32[3 * t + 2];
        }
        const float* pp = &emb[p * NFEAT];
        const float* pq = &emb[q * NFEAT];
        const float* pr = &emb[r * NFEAT];
        float ap = 0.f, an = 0.f;
#pragma unroll 8
        for (int f = 0; f < NFEAT; f++) {
            float pv = pp[f];
            float d1 = pv - pq[f]; ap += d1 * d1;
            float d2 = pv - pr[f]; an += d2 * d2;
        }
        float lv = ap - an + 1.0f;
        s = (lv > 0.f) ? lv : 0.f;
    }
    red[tid] = s;
    __syncthreads();
    for (int o = 128; o > 0; o >>= 1) {
        if (tid < o) red[tid] += red[tid + o];
        __syncthreads();
    }
    if (tid == 0) g_tpart[bid - 8] = red[0];
}

// ---- K3: mma.sync tf32 Gram, UPPER-TRIANGLE tiles only, double-buffered -----
// Block k: a in {k, 511-k}, |dx| columns b>a, tiles of 32 columns.
// Warp tile map (rows x cols), covering all i<=j:
//  w0: r0-31  c0-63  (nu=8)   w1: r32-63 c32-63 (nu=4)
//  w2: r0-31  c64-127(nu=8)   w3: r32-63 c64-127(nu=8)
//  w4: r64-95 c64-127(nu=8)   w5: r96-127 c64-127(nu=8)   w6,w7: gen-only
__global__ void __launch_bounds__(256, 2) k_gram(const float* __restrict__ emb) {
    __shared__ uint32_t s_v[2][NFEAT][VSTRIDE];
    __shared__ float s_m[2][NFEAT];

    const int blk = blockIdx.x;
    const int tid = threadIdx.x;
    const int lane = tid & 31;
    const int w = tid >> 5;

    // warp tile tables
    const int rb_t[8] = {0, 32, 0, 32, 64, 96, 0, 0};
    const int cb_t[8] = {0, 32, 64, 64, 64, 64, 0, 0};
    const int nu_t[8] = {8, 4, 8, 8, 8, 8, 0, 0};
    const int rbase = rb_t[w], cbase = cb_t[w], nu = nu_t[w];

    const int c = lane;        // generated column
    const int f0 = w * 16;     // feature span for gen

    float d[2][8][4];
#pragma unroll
    for (int rt = 0; rt < 2; rt++)
#pragma unroll
        for (int j = 0; j < 8; j++)
#pragma unroll
            for (int e = 0; e < 4; e++) d[rt][j][e] = 0.f;

    int alist[2] = {blk, 511 - blk};
    int tcnt = 0;

    for (int ai = 0; ai < 2; ai++) {
        const int a = alist[ai];
        const int nb = 511 - a;
        if (nb <= 0) continue;

        float4 xa[4];
#pragma unroll
        for (int q = 0; q < 4; q++)
            xa[q] = *(const float4*)&emb[a * NFEAT + f0 + q * 4];

        const int ntile = (nb + 31) >> 5;
        int b = a + 1 + c;
        bool ok = (b < BATCH);
        float4 rb[4];
        {
            const float4* src = (const float4*)&emb[(ok ? b : (BATCH - 1)) * NFEAT + f0];
#pragma unroll
            for (int q = 0; q < 4; q++) rb[q] = src[q];
        }

        for (int t = 0; t < ntile; t++, tcnt++) {
            const int buf = tcnt & 1;
            // gen into buf (safe: sync of previous iter guarantees mma(t-2 parity) done)
#pragma unroll
            for (int q = 0; q < 4; q++) {
                float4 xq = xa[q];
                float4 bq = rb[q];
                float v0 = ok ? fabsf(xq.x - bq.x) : 0.f;
                float v1 = ok ? fabsf(xq.y - bq.y) : 0.f;
                float v2 = ok ? fabsf(xq.z - bq.z) : 0.f;
                float v3 = ok ? fabsf(xq.w - bq.w) : 0.f;
                s_v[buf][f0 + q * 4 + 0][c] = f2tf32(v0);
                s_v[buf][f0 + q * 4 + 1][c] = f2tf32(v1);
                s_v[buf][f0 + q * 4 + 2][c] = f2tf32(v2);
                s_v[buf][f0 + q * 4 + 3][c] = f2tf32(v3);
            }
            __syncthreads();   // the only barrier per tile

            // prefetch next tile (hidden behind mma)
            if (t + 1 < ntile) {
                b = a + 1 + (t + 1) * 32 + c;
                ok = (b < BATCH);
                const float4* src =
                    (const float4*)&emb[(ok ? b : (BATCH - 1)) * NFEAT + f0];
#pragma unroll
                for (int q = 0; q < 4; q++) rb[q] = src[q];
            }

            if (nu > 0) {
#pragma unroll
                for (int ks = 0; ks < 4; ks++) {
                    const int k0 = ks * 8 + (lane & 3);
                    const int ar = lane >> 2;
                    uint32_t afr[2][4];
#pragma unroll
                    for (int rt = 0; rt < 2; rt++) {
                        int rr = rbase + rt * 16 + ar;
                        afr[rt][0] = s_v[buf][rr][k0];
                        afr[rt][1] = s_v[buf][rr + 8][k0];
                        afr[rt][2] = s_v[buf][rr][k0 + 4];
                        afr[rt][3] = s_v[buf][rr + 8][k0 + 4];
                    }
#pragma unroll
                    for (int j = 0; j < 8; j++) {
                        if (j < nu) {
                            int bn = cbase + j * 8 + ar;
                            uint32_t b0 = s_v[buf][bn][k0];
                            uint32_t b1 = s_v[buf][bn][k0 + 4];
                            mma_tf32(d[0][j], afr[0], b0, b1);
                            mma_tf32(d[1][j], afr[1], b0, b1);
                        }
                    }
                }
            }
        }
    }

    // ---- fp32 epilogue: -B * sum_{a in blk} m_a m_a^T (warp tiles only) -----
    __syncthreads();
    {
        int aa = tid >> 7, f = tid & 127;
        s_m[aa][f] = g_m[alist[aa] * NFEAT + f];
    }
    __syncthreads();

    const int gr = lane >> 2, gc = (lane & 3) * 2;
    const float Bf = (float)BATCH;
    if (nu > 0) {
#pragma unroll
        for (int aa = 0; aa < 2; aa++) {
            float am[4];
#pragma unroll
            for (int rt = 0; rt < 2; rt++) {
                am[rt * 2 + 0] = s_m[aa][rbase + rt * 16 + gr];
                am[rt * 2 + 1] = s_m[aa][rbase + rt * 16 + gr + 8];
            }
#pragma unroll
            for (int j = 0; j < 8; j++) {
                if (j < nu) {
                    float bm0 = s_m[aa][cbase + j * 8 + gc];
                    float bm1 = s_m[aa][cbase + j * 8 + gc + 1];
#pragma unroll
                    for (int rt = 0; rt < 2; rt++) {
                        d[rt][j][0] -= Bf * am[rt * 2 + 0] * bm0;
                        d[rt][j][1] -= Bf * am[rt * 2 + 0] * bm1;
                        d[rt][j][2] -= Bf * am[rt * 2 + 1] * bm0;
                        d[rt][j][3] -= Bf * am[rt * 2 + 1] * bm1;
                    }
                }
            }
        }

        float* out = &g_part[blk * NFEAT * NFEAT];
#pragma unroll
        for (int rt = 0; rt < 2; rt++)
#pragma unroll
            for (int j = 0; j < 8; j++) {
                if (j < nu) {
                    int row = rbase + rt * 16 + gr;
                    int col = cbase + j * 8 + gc;
                    out[row * NFEAT + col] = d[rt][j][0];
                    out[row * NFEAT + col + 1] = d[rt][j][1];
                    out[(row + 8) * NFEAT + col] = d[rt][j][2];
                    out[(row + 8) * NFEAT + col + 1] = d[rt][j][3];
                }
            }
    }
}

// ---- K4a: reduction stage 1: 16 slices of 16 slabs each ---------------------
__global__ void k_reduce1(const float* __restrict__ emb) {
    int idx = blockIdx.x * blockDim.x + threadIdx.x;  // 0..16383
    int ks = blockIdx.y;                              // 0..15
    float s = 0.f;
#pragma unroll
    for (int k = ks * 16; k < ks * 16 + 16; k++)
        s += g_part[k * NFEAT * NFEAT + idx];
    g_Sr[ks * NFEAT * NFEAT + idx] = s;
    (void)emb;
}

// ---- K4b: reduction stage 2 + 0.5*Msum Msum^T term --------------------------
__global__ void k_reduce2(const float* __restrict__ emb) {
    int idx = blockIdx.x * blockDim.x + threadIdx.x;  // 0..16383
    int i = idx >> 7, j = idx & 127;
    float s = 0.f;
#pragma unroll
    for (int k = 0; k < NRED1; k++)
        s += g_Sr[k * NFEAT * NFEAT + idx];
    float mi = 0.f, mj = 0.f;
#pragma unroll
    for (int p = 0; p < 8; p++) {
        mi += g_gp[p][i];
        mj += g_gp[p][j];
    }
    g_S[idx] = s + 0.5f * mi * mj;
    (void)emb;
}

// ---- K6: epilogue (reads only i<=j entries of g_S) --------------------------
__global__ void k_final(const float* __restrict__ emb, float* __restrict__ out) {
    __shared__ float q[NFEAT];
    __shared__ float red[256];
    int tid = threadIdx.x;
    if (tid < NFEAT)
        q[tid] = sqrtf(sqrtf(fmaxf(2.f * g_S[tid * NFEAT + tid], 0.f)));
    __syncthreads();

    float s = 0.f;
    int p0 = tid * 32;
    if (p0 < NPAIR) {
        float disc = 65025.f - 8.f * (float)p0;
        int i = (int)((255.f - sqrtf(disc)) * 0.5f);
        if (i < 0) i = 0;
        while (i > 0 && (127 * i - (i * (i - 1)) / 2) > p0) i--;
        while ((127 * (i + 1) - ((i + 1) * i) / 2) <= p0) i++;
        int j = i + 1 + (p0 - (127 * i - (i * (i - 1)) / 2));
        int pend = p0 + 32;
        if (pend > NPAIR) pend = NPAIR;
        for (int p = p0; p < pend; p++) {
            float sij = 2.f * g_S[i * NFEAT + j];
            s += sqrtf(fmaxf(sij, 0.f)) / (q[i] * q[j]);
            if (++j >= NFEAT) { i++; j = i + 1; }
        }
    }
    red[tid] = s;
    __syncthreads();
    for (int o = 128; o > 0; o >>= 1) {
        if (tid < o) red[tid] += red[tid + o];
        __syncthreads();
    }
    if (tid == 0) {
        float tl = 0.f;
        for (int k = 0; k < NTBLK; k++) tl += g_tpart[k];
        out[0] = tl * (1.f / NTRIP) + red[0] * (1.f / NPAIR);
    }
    (void)emb;
}

// ---- launch (k_gram 4th: ncu captures the 4th launch) -----------------------
extern "C" void kernel_launch(void* const* d_in, const int* in_sizes, int n_in,
                              void* d_out, int out_size) {
    const float* emb = (const float*)d_in[0];
    const int* trip = (const int*)d_in[1];
    float* out = (float*)d_out;

    k_means<<<NFEAT, 512>>>(emb);
    k_aux<<<8 + NTBLK, 256>>>(emb, trip);
    dim3 r1(64, NRED1);
    k_gram<<<NGRAM, 256>>>(emb);
    k_reduce1<<<r1, 256>>>(emb);
    k_reduce2<<<64, 256>>>(emb);
    k_final<<<1, 256>>>(emb, out);
}

// round 13
// speedup vs baseline: 2.3765x; 1.0016x over previous
#include <cuda_runtime.h>
#include <cuda_fp16.h>
#include <math.h>
#include <stdint.h>

#define BATCH 512
#define NFEAT 128
#define NTRIP 1024
#define NGRAM 256            // gram blocks (2 antithetic a-values each)
#define NTBLK 4
#define NPAIR 8128
#define VS2 136              // word stride per colpair row (feat dim + 8 pad)
#define NRED1 16             // stage-1 reduction slices

// ---------------- device scratch ---------------------------------------------
__device__ float g_m[BATCH * NFEAT];
__device__ float g_gp[8][NFEAT];                 // partial column sums of m
__device__ float g_part[NGRAM * NFEAT * NFEAT];  // split-K partials (upper tiles)
__device__ float g_Sr[NRED1 * NFEAT * NFEAT];    // stage-1 sums (upper)
__device__ float g_S[NFEAT * NFEAT];             // final S'/2 (upper valid)
__device__ float g_tpart[NTBLK];

__device__ __forceinline__ void mma_f16(float* d, const uint32_t* a,
                                        uint32_t b0, uint32_t b1) {
    asm volatile(
        "mma.sync.aligned.m16n8k16.row.col.f32.f16.f16.f32 "
        "{%0,%1,%2,%3}, {%4,%5,%6,%7}, {%8,%9}, {%0,%1,%2,%3};"
        : "+f"(d[0]), "+f"(d[1]), "+f"(d[2]), "+f"(d[3])
        : "r"(a[0]), "r"(a[1]), "r"(a[2]), "r"(a[3]), "r"(b0), "r"(b1));
}

// ---- K1: row means; 64 blocks x 8 a-values, 512 thr = 128 f x 4 b-quarters --
__global__ void __launch_bounds__(512) k_means(const float* __restrict__ emb) {
    __shared__ float s_red[4][8][NFEAT];
    int tid = threadIdx.x;
    int f = tid & 127, h = tid >> 7;
    int a0 = blockIdx.x * 8;
    float xa[8];
#pragma unroll
    for (int aa = 0; aa < 8; aa++) xa[aa] = emb[(a0 + aa) * NFEAT + f];
    float s[8];
#pragma unroll
    for (int aa = 0; aa < 8; aa++) s[aa] = 0.f;
    int bbase = h * 128;
    for (int b0 = 0; b0 < 128; b0 += 4) {
        float v[4];
#pragma unroll
        for (int u = 0; u < 4; u++) v[u] = emb[(bbase + b0 + u) * NFEAT + f];
#pragma unroll
        for (int u = 0; u < 4; u++)
#pragma unroll
            for (int aa = 0; aa < 8; aa++) s[aa] += fabsf(xa[aa] - v[u]);
    }
#pragma unroll
    for (int aa = 0; aa < 8; aa++) s_red[h][aa][f] = s[aa];
    __syncthreads();
    if (h == 0) {
#pragma unroll
        for (int aa = 0; aa < 8; aa++) {
            float t = s_red[0][aa][f] + s_red[1][aa][f] +
                      s_red[2][aa][f] + s_red[3][aa][f];
            g_m[(a0 + aa) * NFEAT + f] = t * (1.f / BATCH);
        }
    }
}

// ---- K2: partial column sums of m ------------------------------------------
__global__ void k_g(const float* __restrict__ emb) {
    int f = threadIdx.x;
    int p = blockIdx.x;
    float s = 0.f;
#pragma unroll 8
    for (int a = p * 64; a < p * 64 + 64; a++) s += g_m[a * NFEAT + f];
    g_gp[p][f] = s;
    (void)emb;
}

// ---- K3t: triplet loss partials ---------------------------------------------
__global__ void k_triplet(const float* __restrict__ emb,
                          const int* __restrict__ trip32) {
    __shared__ float red[256];
    int tid = threadIdx.x;
    bool is64 = (trip32[1] == 0) && (trip32[3] == 0) &&
                (trip32[5] == 0) && (trip32[7] == 0) &&
                ((trip32[0] | trip32[2] | trip32[4] | trip32[6]) != 0);
    int t = blockIdx.x * 256 + tid;
    float s = 0.f;
    if (t < NTRIP) {
        int p, q, r;
        if (is64) {
            p = trip32[(3 * t + 0) * 2];
            q = trip32[(3 * t + 1) * 2];
            r = trip32[(3 * t + 2) * 2];
        } else {
            p = trip32[3 * t + 0];
            q = trip32[3 * t + 1];
            r = trip32[3 * t + 2];
        }
        const float* pp = &emb[p * NFEAT];
        const float* pq = &emb[q * NFEAT];
        const float* pr = &emb[r * NFEAT];
        float ap = 0.f, an = 0.f;
#pragma unroll 8
        for (int f = 0; f < NFEAT; f++) {
            float pv = pp[f];
            float d1 = pv - pq[f]; ap += d1 * d1;
            float d2 = pv - pr[f]; an += d2 * d2;
        }
        float lv = ap - an + 1.0f;
        s = (lv > 0.f) ? lv : 0.f;
    }
    red[tid] = s;
    __syncthreads();
    for (int o = 128; o > 0; o >>= 1) {
        if (tid < o) red[tid] += red[tid + o];
        __syncthreads();
    }
    if (tid == 0) g_tpart[blockIdx.x] = red[0];
}

// ---- K4: fp16 m16n8k16 Gram, upper-triangle tiles, double-buffered ----------
// s_v word [cp][f] = half2( |x_a-x_{b0}|[f], |x_a-x_{b1}|[f] ), b0=2cp, b1=2cp+1.
// Warp tile map (rows x cols) covering i<=j:
//  w0: r0-31 c0-63 (nu=8)  w1: r32-63 c32-63 (nu=4)  w2: r0-31 c64-127 (nu=8)
//  w3: r32-63 c64-127      w4: r64-95 c64-127        w5: r96-127 c64-127
//  w6,w7: gen-only
__global__ void __launch_bounds__(256, 2) k_gram(const float* __restrict__ emb) {
    __shared__ __align__(16) uint32_t s_v[2][16][VS2];
    __shared__ float s_m[2][NFEAT];

    const int blk = blockIdx.x;
    const int tid = threadIdx.x;
    const int lane = tid & 31;
    const int w = tid >> 5;

    const int rb_t[8] = {0, 32, 0, 32, 64, 96, 0, 0};
    const int cb_t[8] = {0, 32, 64, 64, 64, 64, 0, 0};
    const int nu_t[8] = {8, 4, 8, 8, 8, 8, 0, 0};
    const int rbase = rb_t[w], cbase = cb_t[w], nu = nu_t[w];

    // gen mapping: colpair cp, feats fbase..fbase+7
    const int cp = lane & 15;
    const int fh = lane >> 4;
    const int fbase = w * 16 + fh * 8;

    float d[2][8][4];
#pragma unroll
    for (int rt = 0; rt < 2; rt++)
#pragma unroll
        for (int j = 0; j < 8; j++)
#pragma unroll
            for (int e = 0; e < 4; e++) d[rt][j][e] = 0.f;

    int alist[2] = {blk, 511 - blk};
    int tcnt = 0;

    for (int ai = 0; ai < 2; ai++) {
        const int a = alist[ai];
        const int nb = 511 - a;
        if (nb <= 0) continue;

        float xaf[8];
        {
            float4 t0 = *(const float4*)&emb[a * NFEAT + fbase];
            float4 t1 = *(const float4*)&emb[a * NFEAT + fbase + 4];
            xaf[0] = t0.x; xaf[1] = t0.y; xaf[2] = t0.z; xaf[3] = t0.w;
            xaf[4] = t1.x; xaf[5] = t1.y; xaf[6] = t1.z; xaf[7] = t1.w;
        }

        const int ntile = (nb + 31) >> 5;
        int b0 = a + 1 + 2 * cp, b1 = b0 + 1;
        bool ok0 = (b0 < BATCH), ok1 = (b1 < BATCH);
        float fA[8], fB[8];
        {
            const float4* sA = (const float4*)&emb[(ok0 ? b0 : (BATCH - 1)) * NFEAT + fbase];
            const float4* sB = (const float4*)&emb[(ok1 ? b1 : (BATCH - 1)) * NFEAT + fbase];
            float4 a0v = sA[0], a1v = sA[1], b0v = sB[0], b1v = sB[1];
            fA[0] = a0v.x; fA[1] = a0v.y; fA[2] = a0v.z; fA[3] = a0v.w;
            fA[4] = a1v.x; fA[5] = a1v.y; fA[6] = a1v.z; fA[7] = a1v.w;
            fB[0] = b0v.x; fB[1] = b0v.y; fB[2] = b0v.z; fB[3] = b0v.w;
            fB[4] = b1v.x; fB[5] = b1v.y; fB[6] = b1v.z; fB[7] = b1v.w;
        }

        for (int t = 0; t < ntile; t++, tcnt++) {
            const int buf = tcnt & 1;
            // generate 8 half2 words, 2 x STS.128
            uint32_t hw[8];
#pragma unroll
            for (int e = 0; e < 8; e++) {
                float v0 = ok0 ? fabsf(xaf[e] - fA[e]) : 0.f;
                float v1 = ok1 ? fabsf(xaf[e] - fB[e]) : 0.f;
                __half2 h2 = __floats2half2_rn(v0, v1);
                hw[e] = *(uint32_t*)&h2;
            }
            *(uint4*)&s_v[buf][cp][fbase] =
                make_uint4(hw[0], hw[1], hw[2], hw[3]);
            *(uint4*)&s_v[buf][cp][fbase + 4] =
                make_uint4(hw[4], hw[5], hw[6], hw[7]);
            __syncthreads();

            // prefetch next tile (hidden behind mma)
            if (t + 1 < ntile) {
                b0 = a + 1 + (t + 1) * 32 + 2 * cp;
                b1 = b0 + 1;
                ok0 = (b0 < BATCH);
                ok1 = (b1 < BATCH);
                const float4* sA = (const float4*)&emb[(ok0 ? b0 : (BATCH - 1)) * NFEAT + fbase];
                const float4* sB = (const float4*)&emb[(ok1 ? b1 : (BATCH - 1)) * NFEAT + fbase];
                float4 a0v = sA[0], a1v = sA[1], b0v = sB[0], b1v = sB[1];
                fA[0] = a0v.x; fA[1] = a0v.y; fA[2] = a0v.z; fA[3] = a0v.w;
                fA[4] = a1v.x; fA[5] = a1v.y; fA[6] = a1v.z; fA[7] = a1v.w;
                fB[0] = b0v.x; fB[1] = b0v.y; fB[2] = b0v.z; fB[3] = b0v.w;
                fB[4] = b1v.x; fB[5] = b1v.y; fB[6] = b1v.z; fB[7] = b1v.w;
            }

            if (nu > 0) {
#pragma unroll
                for (int ks = 0; ks < 2; ks++) {
                    const int k0 = ks * 8 + (lane & 3);
                    const int ar = lane >> 2;
                    uint32_t afr[2][4];
#pragma unroll
                    for (int rt = 0; rt < 2; rt++) {
                        int r = rbase + rt * 16 + ar;
                        afr[rt][0] = s_v[buf][k0][r];
                        afr[rt][1] = s_v[buf][k0][r + 8];
                        afr[rt][2] = s_v[buf][k0 + 4][r];
                        afr[rt][3] = s_v[buf][k0 + 4][r + 8];
                    }
#pragma unroll
                    for (int j = 0; j < 8; j++) {
                        if (j < nu) {
                            int n = cbase + j * 8 + ar;
                            uint32_t bf0 = s_v[buf][k0][n];
                            uint32_t bf1 = s_v[buf][k0 + 4][n];
                            mma_f16(d[0][j], afr[0], bf0, bf1);
                            mma_f16(d[1][j], afr[1], bf0, bf1);
                        }
                    }
                }
            }
        }
    }

    // ---- fp32 epilogue: -B * sum_{a in blk} m_a m_a^T (warp tiles only) -----
    __syncthreads();
    {
        int aa = tid >> 7, f = tid & 127;
        s_m[aa][f] = g_m[alist[aa] * NFEAT + f];
    }
    __syncthreads();

    const int gr = lane >> 2, gc = (lane & 3) * 2;
    const float Bf = (float)BATCH;
    if (nu > 0) {
#pragma unroll
        for (int aa = 0; aa < 2; aa++) {
            float am[4];
#pragma unroll
            for (int rt = 0; rt < 2; rt++) {
                am[rt * 2 + 0] = s_m[aa][rbase + rt * 16 + gr];
                am[rt * 2 + 1] = s_m[aa][rbase + rt * 16 + gr + 8];
            }
#pragma unroll
            for (int j = 0; j < 8; j++) {
                if (j < nu) {
                    float bm0 = s_m[aa][cbase + j * 8 + gc];
                    float bm1 = s_m[aa][cbase + j * 8 + gc + 1];
#pragma unroll
                    for (int rt = 0; rt < 2; rt++) {
                        d[rt][j][0] -= Bf * am[rt * 2 + 0] * bm0;
                        d[rt][j][1] -= Bf * am[rt * 2 + 0] * bm1;
                        d[rt][j][2] -= Bf * am[rt * 2 + 1] * bm0;
                        d[rt][j][3] -= Bf * am[rt * 2 + 1] * bm1;
                    }
                }
            }
        }

        float* out = &g_part[blk * NFEAT * NFEAT];
#pragma unroll
        for (int rt = 0; rt < 2; rt++)
#pragma unroll
            for (int j = 0; j < 8; j++) {
                if (j < nu) {
                    int row = rbase + rt * 16 + gr;
                    int col = cbase + j * 8 + gc;
                    out[row * NFEAT + col] = d[rt][j][0];
                    out[row * NFEAT + col + 1] = d[rt][j][1];
                    out[(row + 8) * NFEAT + col] = d[rt][j][2];
                    out[(row + 8) * NFEAT + col + 1] = d[rt][j][3];
                }
            }
    }
}

// ---- K5a: reduction stage 1, upper triangle only ----------------------------
__global__ void k_reduce1(const float* __restrict__ emb) {
    int idx = blockIdx.x * blockDim.x + threadIdx.x;  // 0..16383
    int ks = blockIdx.y;                              // 0..15
    int i = idx >> 7, j = idx & 127;
    float s = 0.f;
    if (j >= i) {
#pragma unroll
        for (int k = ks * 16; k < ks * 16 + 16; k++)
            s += g_part[k * NFEAT * NFEAT + idx];
    }
    g_Sr[ks * NFEAT * NFEAT + idx] = s;
    (void)emb;
}

// ---- K5b: reduction stage 2 + 0.5*Msum Msum^T (upper only) ------------------
__global__ void k_reduce2(const float* __restrict__ emb) {
    int idx = blockIdx.x * blockDim.x + threadIdx.x;
    int i = idx >> 7, j = idx & 127;
    float s = 0.f;
    if (j >= i) {
#pragma unroll
        for (int k = 0; k < NRED1; k++)
            s += g_Sr[k * NFEAT * NFEAT + idx];
        float mi = 0.f, mj = 0.f;
#pragma unroll
        for (int p = 0; p < 8; p++) {
            mi += g_gp[p][i];
            mj += g_gp[p][j];
        }
        s += 0.5f * mi * mj;
    }
    g_S[idx] = s;
    (void)emb;
}

// ---- K6: epilogue (reads only i<=j entries of g_S) --------------------------
__global__ void k_final(const float* __restrict__ emb, float* __restrict__ out) {
    __shared__ float q[NFEAT];
    __shared__ float red[256];
    int tid = threadIdx.x;
    if (tid < NFEAT)
        q[tid] = sqrtf(sqrtf(fmaxf(2.f * g_S[tid * NFEAT + tid], 0.f)));
    __syncthreads();

    float s = 0.f;
    int p0 = tid * 32;
    if (p0 < NPAIR) {
        float disc = 65025.f - 8.f * (float)p0;
        int i = (int)((255.f - sqrtf(disc)) * 0.5f);
        if (i < 0) i = 0;
        while (i > 0 && (127 * i - (i * (i - 1)) / 2) > p0) i--;
        while ((127 * (i + 1) - ((i + 1) * i) / 2) <= p0) i++;
        int j = i + 1 + (p0 - (127 * i - (i * (i - 1)) / 2));
        int pend = p0 + 32;
        if (pend > NPAIR) pend = NPAIR;
        for (int p = p0; p < pend; p++) {
            float sij = 2.f * g_S[i * NFEAT + j];
            s += sqrtf(fmaxf(sij, 0.f)) / (q[i] * q[j]);
            if (++j >= NFEAT) { i++; j = i + 1; }
        }
    }
    red[tid] = s;
    __syncthreads();
    for (int o = 128; o > 0; o >>= 1) {
        if (tid < o) red[tid] += red[tid + o];
        __syncthreads();
    }
    if (tid == 0) {
        float tl = 0.f;
        for (int k = 0; k < NTBLK; k++) tl += g_tpart[k];
        out[0] = tl * (1.f / NTRIP) + red[0] * (1.f / NPAIR);
    }
    (void)emb;
}

// ---- launch (k_gram 4th: ncu captures the 4th launch) -----------------------
extern "C" void kernel_launch(void* const* d_in, const int* in_sizes, int n_in,
                              void* d_out, int out_size) {
    const float* emb = (const float*)d_in[0];
    const int* trip = (const int*)d_in[1];
    float* out = (float*)d_out;

    k_means<<<64, 512>>>(emb);
    k_g<<<8, NFEAT>>>(emb);
    k_triplet<<<NTBLK, 256>>>(emb, trip);
    k_gram<<<NGRAM, 256>>>(emb);
    dim3 r1(64, NRED1);
    k_reduce1<<<r1, 256>>>(emb);
    k_reduce2<<<64, 256>>>(emb);
    k_final<<<1, 256>>>(emb, out);
}